// round 10
// baseline (speedup 1.0000x reference)
#include <cuda_runtime.h>
#include <cstdint>

// YOLO head decode: x[32, 3*85, 80, 80] fp32 -> out[32, 3*80*80, 85] fp32
//   c=0: (sigmoid(v) + grid_x) * 640^2      c=1: (sigmoid(v) + grid_y) * 640^2
//   c=2: exp(v) * anchor_w[a] * 640^2       c=3: exp(v) * anchor_h[a] * 640^2
//   c>=4: sigmoid(v)
//
// R9: big-tile variant. TILE=256 locations x 85 channels per CTA
// (512 threads, 87KB dynamic smem, 2 CTAs/SM). Each CTA reads 85 chunks of
// 1KB (4x longer DRAM bursts than R5/R8) and writes ONE 87KB contiguous
// chunk via TMA bulk store. Tests the hypothesis that the config-invariant
// 6.2TB/s cap comes from too many short scattered streams.

#define NBATCH   32
#define NANCH    3
#define NCH      85                  // C+5
#define SPATIAL  6400                // 80*80
#define GW       80
#define TILE     256                 // spatial locations per block
#define NTILES   (SPATIAL / TILE)    // 25
#define THREADS  512
#define ELEMS    (TILE * NCH)        // 21760 floats
#define ELEMS4   (ELEMS / 4)         // 5440 float4
#define NBATCHJ  11                  // ceil(5440/512)
#define QPC      (TILE / 4)          // float4 per channel row = 64
#define SCALE    409600.0f           // 640*640
#define SMEM_BYTES (ELEMS * 4)       // 87040

__device__ __forceinline__ float fast_sigmoid(float x)
{
    float t;
    asm("tanh.approx.f32 %0, %1;" : "=f"(t) : "f"(0.5f * x));
    return fmaf(0.5f, t, 0.5f);
}

__global__ __launch_bounds__(THREADS, 2)
void yolo_decode_kernel(const float* __restrict__ in, float* __restrict__ out)
{
    extern __shared__ __align__(128) float sm[];   // 87040 B

    const int bt   = blockIdx.x;
    const int tile = bt % NTILES;
    const int na   = bt / NTILES;      // 0..95 = n*3 + a
    const int a    = na % NANCH;

    const float awS = ((a == 0) ? 10.0f : (a == 1) ? 16.0f : 33.0f) * SCALE;
    const float ahS = ((a == 0) ? 13.0f : (a == 1) ? 30.0f : 23.0f) * SCALE;

    const int s_base   = tile * TILE;
    // input elem (n, a*85+c, s): (na*85 + c)*6400 + s
    const int base_in  = (na * NCH) * SPATIAL + s_base;
    // output elem (n, a*6400+s, c): (na*6400 + s)*85 + c
    const int base_out = (na * SPATIAL + s_base) * NCH;

    const float4* __restrict__ in4 = reinterpret_cast<const float4*>(in);
    const int base4 = base_in >> 2;    // s_base multiple of 4

    // ---- Phase 1a: front-batch up to 11 independent LDG.128 per thread.
    // float4 index q in [0,5440): c = q/64 (channel), sq = q%64 (quad within
    // the 256-float = 1KB channel row). Address: base4 + c*1600 + sq.
    // 32 consecutive lanes cover 512 contiguous bytes -> fully coalesced.
    float4 v[NBATCHJ];
    #pragma unroll
    for (int j = 0; j < NBATCHJ; j++) {
        const int q = threadIdx.x + j * THREADS;
        if (q < ELEMS4) {
            const int c  = q >> 6;
            const int sq = q & (QPC - 1);
            v[j] = in4[base4 + c * (SPATIAL / 4) + sq];
        }
    }

    // ---- Phase 1b: transform + transposed STS (sm[s0*85 + c]).
    #pragma unroll
    for (int j = 0; j < NBATCHJ; j++) {
        const int q = threadIdx.x + j * THREADS;
        if (q < ELEMS4) {
            const int c  = q >> 6;
            const int s0 = (q & (QPC - 1)) << 2;
            const float vv[4] = { v[j].x, v[j].y, v[j].z, v[j].w };
            #pragma unroll
            for (int k = 0; k < 4; k++) {
                const float x = vv[k];
                float r;
                if (c >= 4) {
                    r = fast_sigmoid(x);
                } else if (c == 0) {
                    const int sabs = s_base + s0 + k;
                    r = (fast_sigmoid(x) + (float)(sabs % GW)) * SCALE;
                } else if (c == 1) {
                    const int sabs = s_base + s0 + k;
                    r = (fast_sigmoid(x) + (float)(sabs / GW)) * SCALE;
                } else if (c == 2) {
                    r = __expf(x) * awS;
                } else { // c == 3
                    r = __expf(x) * ahS;
                }
                sm[(s0 + k) * NCH + c] = r;
            }
        }
    }

    __syncthreads();

    // ---- Phase 2: single TMA bulk store of the contiguous 87040-byte chunk.
    if (threadIdx.x == 0) {
        uint32_t smem_addr;
        asm("{ .reg .u64 t; cvta.to.shared.u64 t, %1; cvt.u32.u64 %0, t; }"
            : "=r"(smem_addr) : "l"((const void*)sm));
        asm volatile("fence.proxy.async.shared::cta;" ::: "memory");
        asm volatile(
            "cp.async.bulk.global.shared::cta.bulk_group [%0], [%1], %2;"
            :: "l"(out + base_out), "r"(smem_addr), "r"((int)SMEM_BYTES)
            : "memory");
        asm volatile("cp.async.bulk.commit_group;" ::: "memory");
        // Drain before CTA exit: next CTA on this SM reuses the smem slot.
        asm volatile("cp.async.bulk.wait_group 0;" ::: "memory");
    }
}

extern "C" void kernel_launch(void* const* d_in, const int* in_sizes, int n_in,
                              void* d_out, int out_size)
{
    const float* x   = (const float*)d_in[0];
    float*       out = (float*)d_out;
    (void)in_sizes; (void)n_in; (void)out_size;

    // Dynamic smem above the 48KB static limit (idempotent, capture-safe).
    cudaFuncSetAttribute(yolo_decode_kernel,
                         cudaFuncAttributeMaxDynamicSharedMemorySize,
                         SMEM_BYTES);

    const int grid = NBATCH * NANCH * NTILES;   // 96*25 = 2400
    yolo_decode_kernel<<<grid, THREADS, SMEM_BYTES>>>(x, out);
}

// round 11
// speedup vs baseline: 1.0066x; 1.0066x over previous
#include <cuda_runtime.h>
#include <cstdint>

// YOLO head decode: x[32, 3*85, 80, 80] fp32 -> out[32, 3*80*80, 85] fp32
//   c=0: (sigmoid(v) + grid_x) * 640^2      c=1: (sigmoid(v) + grid_y) * 640^2
//   c=2: exp(v) * anchor_w[a] * 640^2       c=3: exp(v) * anchor_h[a] * 640^2
//   c>=4: sigmoid(v)
//
// R11: revert to the R5 best shape (TILE=64, 256 threads, 6 LDG.128 front
// batch, smem transpose, single TMA bulk store) + __ldcs streaming loads.
// Input is read exactly once -> evict-first keeps those sectors from
// displacing pending output writes in the 126MB L2 (measured DRAM traffic
// 363MB < logical 418MB shows L2 write-buffering is active and valuable).

#define NBATCH   32
#define NANCH    3
#define NCH      85                  // C+5
#define SPATIAL  6400                // 80*80
#define GW       80
#define TILE     64                  // spatial locations per block
#define NTILES   (SPATIAL / TILE)    // 100
#define THREADS  256
#define ELEMS    (TILE * NCH)        // 5440 floats
#define ELEMS4   (ELEMS / 4)         // 1360 float4
#define NBATCHJ  6                   // ceil(1360/256)
#define SCALE    409600.0f           // 640*640

__device__ __forceinline__ float fast_sigmoid(float x)
{
    float t;
    asm("tanh.approx.f32 %0, %1;" : "=f"(t) : "f"(0.5f * x));
    return fmaf(0.5f, t, 0.5f);
}

__global__ __launch_bounds__(THREADS)
void yolo_decode_kernel(const float* __restrict__ in, float* __restrict__ out)
{
    __shared__ __align__(128) float sm[ELEMS];   // 21.76 KB

    const int bt   = blockIdx.x;
    const int tile = bt % NTILES;
    const int na   = bt / NTILES;      // 0..95 = n*3 + a
    const int a    = na % NANCH;

    const float awS = ((a == 0) ? 10.0f : (a == 1) ? 16.0f : 33.0f) * SCALE;
    const float ahS = ((a == 0) ? 13.0f : (a == 1) ? 30.0f : 23.0f) * SCALE;

    const int s_base   = tile * TILE;
    // input elem (n, a*85+c, s): (na*85 + c)*6400 + s
    const int base_in  = (na * NCH) * SPATIAL + s_base;
    // output elem (n, a*6400+s, c): (na*6400 + s)*85 + c
    const int base_out = (na * SPATIAL + s_base) * NCH;

    const float4* __restrict__ in4 = reinterpret_cast<const float4*>(in);
    const int base4 = base_in >> 2;    // multiple of 16 (s_base mult of 64)

    // ---- Phase 1a: front-batch 6 independent streaming LDG.128 per thread.
    // float4 index q in [0,1360): c = q>>4, sq = q&15 (quad within the
    // 64-float channel row). Address: base4 + c*1600 + sq.
    float4 v[NBATCHJ];
    #pragma unroll
    for (int j = 0; j < NBATCHJ; j++) {
        const int q = threadIdx.x + j * THREADS;
        if (q < ELEMS4) {
            const int c  = q >> 4;
            const int sq = q & 15;
            v[j] = __ldcs(&in4[base4 + c * (SPATIAL / 4) + sq]);
        }
    }

    // ---- Phase 1b: transform + transposed STS (sm[s0*85 + c]).
    #pragma unroll
    for (int j = 0; j < NBATCHJ; j++) {
        const int q = threadIdx.x + j * THREADS;
        if (q < ELEMS4) {
            const int c  = q >> 4;
            const int s0 = (q & 15) << 2;
            const float vv[4] = { v[j].x, v[j].y, v[j].z, v[j].w };
            #pragma unroll
            for (int k = 0; k < 4; k++) {
                const float x = vv[k];
                float r;
                if (c >= 4) {
                    r = fast_sigmoid(x);
                } else if (c == 0) {
                    const int sabs = s_base + s0 + k;
                    r = (fast_sigmoid(x) + (float)(sabs % GW)) * SCALE;
                } else if (c == 1) {
                    const int sabs = s_base + s0 + k;
                    r = (fast_sigmoid(x) + (float)(sabs / GW)) * SCALE;
                } else if (c == 2) {
                    r = __expf(x) * awS;
                } else { // c == 3
                    r = __expf(x) * ahS;
                }
                sm[(s0 + k) * NCH + c] = r;
            }
        }
    }

    __syncthreads();

    // ---- Phase 2: single TMA bulk store of the contiguous 21760-byte chunk.
    if (threadIdx.x == 0) {
        uint32_t smem_addr;
        asm("{ .reg .u64 t; cvta.to.shared.u64 t, %1; cvt.u32.u64 %0, t; }"
            : "=r"(smem_addr) : "l"((const void*)sm));
        asm volatile("fence.proxy.async.shared::cta;" ::: "memory");
        asm volatile(
            "cp.async.bulk.global.shared::cta.bulk_group [%0], [%1], %2;"
            :: "l"(out + base_out), "r"(smem_addr), "r"((int)(ELEMS * 4))
            : "memory");
        asm volatile("cp.async.bulk.commit_group;" ::: "memory");
        // Drain before CTA exit: next CTA on this SM reuses the smem slot.
        asm volatile("cp.async.bulk.wait_group 0;" ::: "memory");
    }
}

extern "C" void kernel_launch(void* const* d_in, const int* in_sizes, int n_in,
                              void* d_out, int out_size)
{
    const float* x   = (const float*)d_in[0];
    float*       out = (float*)d_out;
    (void)in_sizes; (void)n_in; (void)out_size;

    const int grid = NBATCH * NANCH * NTILES;   // 9600
    yolo_decode_kernel<<<grid, THREADS>>>(x, out);
}

// round 12
// speedup vs baseline: 1.0275x; 1.0208x over previous
#include <cuda_runtime.h>
#include <cstdint>

// YOLO head decode: x[32, 3*85, 80, 80] fp32 -> out[32, 3*80*80, 85] fp32
//   c=0: (sigmoid(v) + grid_x) * 640^2      c=1: (sigmoid(v) + grid_y) * 640^2
//   c=2: exp(v) * anchor_w[a] * 640^2       c=3: exp(v) * anchor_h[a] * 640^2
//   c>=4: sigmoid(v)
//
// R12: R5 shape with BOTH directions streaming-class: __ldcs input loads +
// st.global.cs (evict-first) float4 output stores replacing the TMA bulk
// store. Probes the write-side L2 policy — the only memory-path knob not yet
// tested. Kernel is at ~93% of achievable DRAM R/W-mix throughput; if this
// is flat, R5-class is final.

#define NBATCH   32
#define NANCH    3
#define NCH      85                  // C+5
#define SPATIAL  6400                // 80*80
#define GW       80
#define TILE     64                  // spatial locations per block
#define NTILES   (SPATIAL / TILE)    // 100
#define THREADS  256
#define ELEMS    (TILE * NCH)        // 5440 floats
#define ELEMS4   (ELEMS / 4)         // 1360 float4
#define NBATCHJ  6                   // ceil(1360/256)
#define SCALE    409600.0f           // 640*640

__device__ __forceinline__ float fast_sigmoid(float x)
{
    float t;
    asm("tanh.approx.f32 %0, %1;" : "=f"(t) : "f"(0.5f * x));
    return fmaf(0.5f, t, 0.5f);
}

__global__ __launch_bounds__(THREADS)
void yolo_decode_kernel(const float* __restrict__ in, float* __restrict__ out)
{
    __shared__ __align__(128) float sm[ELEMS];   // 21.76 KB

    const int bt   = blockIdx.x;
    const int tile = bt % NTILES;
    const int na   = bt / NTILES;      // 0..95 = n*3 + a
    const int a    = na % NANCH;

    const float awS = ((a == 0) ? 10.0f : (a == 1) ? 16.0f : 33.0f) * SCALE;
    const float ahS = ((a == 0) ? 13.0f : (a == 1) ? 30.0f : 23.0f) * SCALE;

    const int s_base   = tile * TILE;
    // input elem (n, a*85+c, s): (na*85 + c)*6400 + s
    const int base_in  = (na * NCH) * SPATIAL + s_base;
    // output elem (n, a*6400+s, c): (na*6400 + s)*85 + c
    const int base_out = (na * SPATIAL + s_base) * NCH;

    const float4* __restrict__ in4 = reinterpret_cast<const float4*>(in);
    const int base4 = base_in >> 2;

    // ---- Phase 1a: front-batch 6 independent streaming LDG.128 per thread.
    float4 v[NBATCHJ];
    #pragma unroll
    for (int j = 0; j < NBATCHJ; j++) {
        const int q = threadIdx.x + j * THREADS;
        if (q < ELEMS4) {
            const int c  = q >> 4;
            const int sq = q & 15;
            v[j] = __ldcs(&in4[base4 + c * (SPATIAL / 4) + sq]);
        }
    }

    // ---- Phase 1b: transform + transposed STS (sm[s0*85 + c]).
    #pragma unroll
    for (int j = 0; j < NBATCHJ; j++) {
        const int q = threadIdx.x + j * THREADS;
        if (q < ELEMS4) {
            const int c  = q >> 4;
            const int s0 = (q & 15) << 2;
            const float vv[4] = { v[j].x, v[j].y, v[j].z, v[j].w };
            #pragma unroll
            for (int k = 0; k < 4; k++) {
                const float x = vv[k];
                float r;
                if (c >= 4) {
                    r = fast_sigmoid(x);
                } else if (c == 0) {
                    const int sabs = s_base + s0 + k;
                    r = (fast_sigmoid(x) + (float)(sabs % GW)) * SCALE;
                } else if (c == 1) {
                    const int sabs = s_base + s0 + k;
                    r = (fast_sigmoid(x) + (float)(sabs / GW)) * SCALE;
                } else if (c == 2) {
                    r = __expf(x) * awS;
                } else { // c == 3
                    r = __expf(x) * ahS;
                }
                sm[(s0 + k) * NCH + c] = r;
            }
        }
    }

    __syncthreads();

    // ---- Phase 2: contiguous float4 streaming stores (evict-first).
    const float4* __restrict__ sm4  = reinterpret_cast<const float4*>(sm);
    float4*       __restrict__ out4 = reinterpret_cast<float4*>(out + base_out);
    #pragma unroll
    for (int j = 0; j < NBATCHJ; j++) {
        const int q = threadIdx.x + j * THREADS;
        if (q < ELEMS4) __stcs(&out4[q], sm4[q]);
    }
}

extern "C" void kernel_launch(void* const* d_in, const int* in_sizes, int n_in,
                              void* d_out, int out_size)
{
    const float* x   = (const float*)d_in[0];
    float*       out = (float*)d_out;
    (void)in_sizes; (void)n_in; (void)out_size;

    const int grid = NBATCH * NANCH * NTILES;   // 9600
    yolo_decode_kernel<<<grid, THREADS>>>(x, out);
}